// round 9
// baseline (speedup 1.0000x reference)
#include <cuda_runtime.h>
#include <cuda_bf16.h>
#include <stdint.h>

// ---------------- problem constants ----------------
#define I_N 1024
#define O_N 36
#define C_N 1024
#define W_N 60
#define D_N 64
#define MARGIN 0.2f

#define IMG_PER_CTA 7
#define NCTA 147            // ceil(1024/7)
#define THREADS 512         // 16 warps; warp w owns m16-tile w (256 rows total)
#define CAP_BATCH 8         // captions per B buffer (8KB each, bf16)
#define NBATCH (C_N / CAP_BATCH)

// ---------------- smem layout (bytes from 1024-aligned base) ----------------
#define OFF_A    0          // 256 rows x 128B (bf16)            = 32768
#define OFF_B    32768      // 2 bufs x 64KB (8 captions each)   = 131072
#define OFF_RMAX 163840     // 8 x 256 floats                    = 8192
#define OFF_INV  172032     // 7 floats
#define SMEM_BYTES (172064 + 1024)

// ---------------- device globals ----------------
__device__ __nv_bfloat16 gA [(size_t)I_N * O_N * D_N];
__device__ __nv_bfloat16 gBh[(size_t)C_N * 64 * D_N];   // words padded to 64 w/ duplicate of last valid word
__device__ float g_scores[(size_t)I_N * C_N];
__device__ float g_diag[I_N];
__device__ float g_partial[I_N];

// ---------------- helpers ----------------
__device__ __forceinline__ uint32_t smem_u32(const void* p) {
    uint32_t a;
    asm("{ .reg .u64 t; cvta.to.shared.u64 t, %1; cvt.u32.u64 %0, t; }" : "=r"(a) : "l"(p));
    return a;
}
#define SW128(off) ((off) ^ (((off) >> 3) & 0x70))

__device__ __forceinline__ void ldsm4(uint32_t* r, uint32_t addr) {
    asm volatile("ldmatrix.sync.aligned.m8n8.x4.shared.b16 {%0,%1,%2,%3}, [%4];"
                 : "=r"(r[0]), "=r"(r[1]), "=r"(r[2]), "=r"(r[3]) : "r"(addr));
}
__device__ __forceinline__ void mma16816(float* d, const uint32_t* a, const uint32_t* b) {
    asm volatile(
        "mma.sync.aligned.m16n8k16.row.col.f32.bf16.bf16.f32 "
        "{%0,%1,%2,%3}, {%4,%5,%6,%7}, {%8,%9}, {%0,%1,%2,%3};"
        : "+f"(d[0]), "+f"(d[1]), "+f"(d[2]), "+f"(d[3])
        : "r"(a[0]), "r"(a[1]), "r"(a[2]), "r"(a[3]), "r"(b[0]), "r"(b[1]));
}
#define CP16(dst, src) \
    asm volatile("cp.async.cg.shared.global [%0], [%1], 16;" :: "r"(dst), "l"(src))
#define CP_COMMIT()  asm volatile("cp.async.commit_group;" ::: "memory")
#define CP_WAIT(n)   asm volatile("cp.async.wait_group %0;" :: "n"(n) : "memory")

// ---------------- precompute ----------------
extern "C" __global__ void convA_kernel(const float* __restrict__ im)
{
    size_t idx = (size_t)blockIdx.x * blockDim.x + threadIdx.x;
    if (idx >= (size_t)I_N * O_N * D_N) return;
    gA[idx] = __float2bfloat16(im[idx]);
}

// Pad words [clen, 64) with a COPY of word clen-1: max over any computed
// superset of columns equals the true max -> no masking needed downstream.
extern "C" __global__ void convB_kernel(const float* __restrict__ s,
                                        const int* __restrict__ s_l)
{
    size_t idx = (size_t)blockIdx.x * blockDim.x + threadIdx.x;
    if (idx >= (size_t)C_N * 64 * D_N) return;
    int d = idx & 63;
    int w = ((int)idx >> 6) & 63;
    int c = (int)(idx >> 12);
    int clen = s_l[c];
    int ws = (w < clen) ? w : (clen - 1);
    gBh[idx] = __float2bfloat16(s[((size_t)c * W_N + ws) * D_N + d]);
}

// ---------------- main xattn-scores kernel ----------------
extern "C" __global__ void __launch_bounds__(THREADS, 1)
xattn_kernel(const int* __restrict__ im_l, const int* __restrict__ s_l)
{
    extern __shared__ char smraw[];
    const uint32_t raw_u = smem_u32(smraw);
    const uint32_t abase = (raw_u + 1023u) & ~1023u;
    char* base = smraw + (abase - raw_u);

    const int tid  = threadIdx.x;
    const int wid  = tid >> 5;          // 0..15, owns m16-tile wid
    const int lane = tid & 31;
    const int img0 = blockIdx.x * IMG_PER_CTA;
    const int n_img = (I_N - img0 < IMG_PER_CTA) ? (I_N - img0) : IMG_PER_CTA;

    float* rmax = (float*)(base + OFF_RMAX);   // [8][256]
    float* inv  = (float*)(base + OFF_INV);
    if (tid < n_img)
        inv[tid] = 1.0f / ((float)im_l[img0 + tid] + 1e-6f);

    // ---- stage A into swizzled smem; zero-pad rows >= n_img*36 ----
    {
        const int vchunks = n_img * O_N * 8;
        const uint4* ga = (const uint4*)(gA + (size_t)img0 * O_N * D_N);
        const uint4 z = make_uint4(0, 0, 0, 0);
        #pragma unroll
        for (int t = tid; t < 2048; t += THREADS) {
            uint32_t off = SW128((uint32_t)(t * 16));
            *(uint4*)(base + OFF_A + off) = (t < vchunks) ? ga[t] : z;
        }
    }

    // ---- prefetch B batch 0 (captions 0..7): 64 KB ----
    {
        const char* sh = (const char*)(gBh);
        uint32_t dst = abase + OFF_B;
        #pragma unroll
        for (int t = tid; t < 4096; t += THREADS) {
            uint32_t off = SW128((uint32_t)(t * 16));
            CP16(dst + off, sh + t * 16);
        }
    }
    CP_COMMIT();
    __syncthreads();

    // ---- ldmatrix addressing invariants ----
    const uint32_t xr    = (uint32_t)((lane & 7) << 4);
    const uint32_t aColB = (uint32_t)((lane >> 4) << 4);
    const uint32_t aRow  = (uint32_t)(wid * 16 + (lane & 15));
    // B ldsm4: lane L -> row (L&7), matrix (L>>3); one x4 covers 2 k-steps.
    const uint32_t bRowOff = (uint32_t)((lane & 7) * 128);
    const uint32_t bMat    = (uint32_t)((lane >> 3) << 4);

    // epilogue mapping: quad q (0..55) -> (image q>>3, caption q&7)
    const int quad = tid >> 2;
    const int ql   = tid & 3;
    const int eimg = quad >> 3;
    const int ecap = quad & 7;

    // ---- A fragments resident in registers (one m-tile per warp) ----
    uint32_t af[4][4];
    #pragma unroll
    for (int k = 0; k < 4; ++k)
        ldsm4(af[k], abase + OFF_A + aRow * 128 + ((aColB + (uint32_t)(k * 32)) ^ xr));

    for (int cc = 0; cc < NBATCH; ++cc) {
        // prefetch next batch (64 KB)
        if (cc + 1 < NBATCH) {
            const char* sh = (const char*)(gBh + (size_t)(cc + 1) * 32768);
            uint32_t dst = abase + OFF_B + (uint32_t)((cc + 1) & 1) * 65536;
            #pragma unroll
            for (int t = tid; t < 4096; t += THREADS) {
                uint32_t off = SW128((uint32_t)(t * 16));
                CP16(dst + off, sh + t * 16);
            }
            CP_COMMIT();
            CP_WAIT(1);
        } else {
            CP_WAIT(0);
        }
        __syncthreads();   // batch (cc) B ready; prev-batch rmax reads complete

        #pragma unroll
        for (int j = 0; j < CAP_BATCH; ++j) {
            const int c = CAP_BATCH * cc + j;
            const int clen = __ldg(&s_l[c]);
            const int nlim = (clen + 7) >> 3;      // n8 tiles to compute
            const uint32_t bh_base = abase + OFF_B + (uint32_t)((cc & 1) << 16)
                                    + (uint32_t)(j << 13);

            float mx[2] = { -1e30f, -1e30f };

            #pragma unroll
            for (int p = 0; p < 4; ++p) {
                const int n0 = 2 * p;
                if (n0 < nlim) {
                    const bool has2 = (n0 + 1) < nlim;
                    uint32_t bf0[2][4], bf1[2][4];
                    #pragma unroll
                    for (int kp = 0; kp < 2; ++kp)
                        ldsm4(bf0[kp], bh_base + (uint32_t)(n0 * 1024) + bRowOff
                                      + (((uint32_t)(kp * 64) + bMat) ^ xr));
                    if (has2) {
                        #pragma unroll
                        for (int kp = 0; kp < 2; ++kp)
                            ldsm4(bf1[kp], bh_base + (uint32_t)((n0 + 1) * 1024) + bRowOff
                                          + (((uint32_t)(kp * 64) + bMat) ^ xr));
                    }

                    // two k-chains per tile (k0,k1 | k2,k3) -> 4 independent
                    // MMA chains per tile pair, halving exposed chain latency
                    float accA0[4], accB0[4], accA1[4], accB1[4];
                    #pragma unroll
                    for (int q = 0; q < 4; ++q) {
                        accA0[q] = 0.0f; accB0[q] = 0.0f;
                        accA1[q] = 0.0f; accB1[q] = 0.0f;
                    }

                    mma16816(accA0, af[0], &bf0[0][0]);
                    mma16816(accB0, af[2], &bf0[1][0]);
                    if (has2) {
                        mma16816(accA1, af[0], &bf1[0][0]);
                        mma16816(accB1, af[2], &bf1[1][0]);
                    }
                    mma16816(accA0, af[1], &bf0[0][2]);
                    mma16816(accB0, af[3], &bf0[1][2]);
                    if (has2) {
                        mma16816(accA1, af[1], &bf1[0][2]);
                        mma16816(accB1, af[3], &bf1[1][2]);
                    }

                    // merge chains (sum over k) then fold into max
                    mx[0] = fmaxf(mx[0], fmaxf(accA0[0] + accB0[0], accA0[1] + accB0[1]));
                    mx[1] = fmaxf(mx[1], fmaxf(accA0[2] + accB0[2], accA0[3] + accB0[3]));
                    if (has2) {
                        mx[0] = fmaxf(mx[0], fmaxf(accA1[0] + accB1[0], accA1[1] + accB1[1]));
                        mx[1] = fmaxf(mx[1], fmaxf(accA1[2] + accB1[2], accA1[3] + accB1[3]));
                    }
                }
            }

            // quad reduce (lanes sharing the same rows)
            #pragma unroll
            for (int q = 0; q < 2; ++q) {
                mx[q] = fmaxf(mx[q], __shfl_xor_sync(0xFFFFFFFFu, mx[q], 1));
                mx[q] = fmaxf(mx[q], __shfl_xor_sync(0xFFFFFFFFu, mx[q], 2));
            }
            if ((lane & 3) == 0) {
                float* rj = rmax + j * 256;
                const int row0 = wid * 16 + (lane >> 2);
                rj[row0]     = mx[0];
                rj[row0 + 8] = mx[1];
            }
        }
        __syncthreads();   // all 8 captions' rmax ready

        // ---- quad-parallel score epilogue: quad q -> (image q>>3, caption q&7)
        // guards are warp-uniform (img constant within each warp), full-mask shfl safe
        if (quad < 56 && eimg < n_img) {
            const float* rj = rmax + ecap * 256 + eimg * O_N;
            float v = 0.0f;
            #pragma unroll
            for (int i = 0; i < 9; ++i)
                v += rj[ql + 4 * i];
            v += __shfl_xor_sync(0xFFFFFFFFu, v, 1);
            v += __shfl_xor_sync(0xFFFFFFFFu, v, 2);
            if (ql == 0)
                g_scores[(size_t)(img0 + eimg) * C_N + CAP_BATCH * cc + ecap] =
                    v * inv[eimg];
        }
        // WAR on rmax covered by next batch's B-ready syncthreads
    }
}

// ---------------- loss epilogue ----------------
extern "C" __global__ void diag_kernel()
{
    int i = blockIdx.x * blockDim.x + threadIdx.x;
    if (i < I_N) g_diag[i] = g_scores[(size_t)i * C_N + i];
}

extern "C" __global__ void row_kernel()
{
    const int b = blockIdx.x;
    const int tid = threadIdx.x;
    const float di = g_diag[b];
    float local = 0.0f;
    for (int c = tid; c < C_N; c += blockDim.x) {
        if (c == b) continue;
        float sc = g_scores[(size_t)b * C_N + c];
        local += fmaxf(0.0f, MARGIN + sc - di)
               + fmaxf(0.0f, MARGIN + sc - g_diag[c]);
    }
    __shared__ float buf[128];
    buf[tid] = local;
    __syncthreads();
    for (int s = 64; s > 0; s >>= 1) {
        if (tid < s) buf[tid] += buf[tid + s];
        __syncthreads();
    }
    if (tid == 0) g_partial[b] = buf[0];
}

extern "C" __global__ void final_kernel(float* out)
{
    const int tid = threadIdx.x;
    float local = 0.0f;
    for (int i = tid; i < I_N; i += 256) local += g_partial[i];
    __shared__ float buf[256];
    buf[tid] = local;
    __syncthreads();
    for (int s = 128; s > 0; s >>= 1) {
        if (tid < s) buf[tid] += buf[tid + s];
        __syncthreads();
    }
    if (tid == 0) out[0] = buf[0] * (1.0f / ((float)I_N * (float)C_N));
}

// ---------------- launch ----------------
extern "C" void kernel_launch(void* const* d_in, const int* in_sizes, int n_in,
                              void* d_out, int out_size)
{
    const float* im   = (const float*)d_in[0];
    const float* s    = (const float*)d_in[1];
    const int*   im_l = (const int*)d_in[2];
    const int*   s_l  = (const int*)d_in[3];

    cudaFuncSetAttribute(xattn_kernel,
                         cudaFuncAttributeMaxDynamicSharedMemorySize, SMEM_BYTES);

    convA_kernel<<<(I_N * O_N * D_N + 255) / 256, 256>>>(im);
    convB_kernel<<<(C_N * 64 * D_N + 255) / 256, 256>>>(s, s_l);
    xattn_kernel<<<NCTA, THREADS, SMEM_BYTES>>>(im_l, s_l);
    diag_kernel<<<I_N / 256, 256>>>();
    row_kernel<<<I_N, 128>>>();
    final_kernel<<<1, 256>>>((float*)d_out);
}

// round 10
// speedup vs baseline: 1.0733x; 1.0733x over previous
#include <cuda_runtime.h>
#include <cuda_bf16.h>
#include <stdint.h>

// ---------------- problem constants ----------------
#define I_N 1024
#define O_N 36
#define C_N 1024
#define W_N 60
#define D_N 64
#define MARGIN 0.2f

#define IMG_PER_CTA 7
#define NCTA 147            // ceil(1024/7)
#define THREADS 512         // 16 warps; warp w owns m16-tile w (256 rows total)
#define CAP_BATCH 8         // captions per B buffer (8KB each, bf16)
#define NBATCH (C_N / CAP_BATCH)

// ---------------- smem layout (bytes from 1024-aligned base) ----------------
#define OFF_A    0          // 256 rows x 128B (bf16)            = 32768
#define OFF_B    32768      // 2 bufs x 64KB (8 captions each)   = 131072
#define OFF_RMAX 163840     // 2 bufs x 8 x 256 floats           = 16384
#define OFF_INV  180224     // 7 floats
#define SMEM_BYTES (180256 + 1024)

// ---------------- device globals ----------------
__device__ __nv_bfloat16 gA [(size_t)I_N * O_N * D_N];
__device__ __nv_bfloat16 gBh[(size_t)C_N * 64 * D_N];   // words padded to 64 w/ duplicate of last valid word
__device__ float g_scores[(size_t)I_N * C_N];
__device__ float g_diag[I_N];
__device__ float g_partial[I_N];

// ---------------- helpers ----------------
__device__ __forceinline__ uint32_t smem_u32(const void* p) {
    uint32_t a;
    asm("{ .reg .u64 t; cvta.to.shared.u64 t, %1; cvt.u32.u64 %0, t; }" : "=r"(a) : "l"(p));
    return a;
}
#define SW128(off) ((off) ^ (((off) >> 3) & 0x70))

__device__ __forceinline__ void ldsm4(uint32_t* r, uint32_t addr) {
    asm volatile("ldmatrix.sync.aligned.m8n8.x4.shared.b16 {%0,%1,%2,%3}, [%4];"
                 : "=r"(r[0]), "=r"(r[1]), "=r"(r[2]), "=r"(r[3]) : "r"(addr));
}
__device__ __forceinline__ void mma16816(float* d, const uint32_t* a, const uint32_t* b) {
    asm volatile(
        "mma.sync.aligned.m16n8k16.row.col.f32.bf16.bf16.f32 "
        "{%0,%1,%2,%3}, {%4,%5,%6,%7}, {%8,%9}, {%0,%1,%2,%3};"
        : "+f"(d[0]), "+f"(d[1]), "+f"(d[2]), "+f"(d[3])
        : "r"(a[0]), "r"(a[1]), "r"(a[2]), "r"(a[3]), "r"(b[0]), "r"(b[1]));
}
#define CP16(dst, src) \
    asm volatile("cp.async.cg.shared.global [%0], [%1], 16;" :: "r"(dst), "l"(src))
#define CP_COMMIT()  asm volatile("cp.async.commit_group;" ::: "memory")
#define CP_WAIT(n)   asm volatile("cp.async.wait_group %0;" :: "n"(n) : "memory")

// ---------------- precompute ----------------
extern "C" __global__ void convA_kernel(const float* __restrict__ im)
{
    size_t idx = (size_t)blockIdx.x * blockDim.x + threadIdx.x;
    if (idx >= (size_t)I_N * O_N * D_N) return;
    gA[idx] = __float2bfloat16(im[idx]);
}

// Pad words [clen, 64) with a COPY of word clen-1: max over any computed
// superset of columns equals the true max -> no masking needed downstream.
extern "C" __global__ void convB_kernel(const float* __restrict__ s,
                                        const int* __restrict__ s_l)
{
    size_t idx = (size_t)blockIdx.x * blockDim.x + threadIdx.x;
    if (idx >= (size_t)C_N * 64 * D_N) return;
    int d = idx & 63;
    int w = ((int)idx >> 6) & 63;
    int c = (int)(idx >> 12);
    int clen = s_l[c];
    int ws = (w < clen) ? w : (clen - 1);
    gBh[idx] = __float2bfloat16(s[((size_t)c * W_N + ws) * D_N + d]);
}

// ---------------- main xattn-scores kernel ----------------
extern "C" __global__ void __launch_bounds__(THREADS, 1)
xattn_kernel(const int* __restrict__ im_l, const int* __restrict__ s_l)
{
    extern __shared__ char smraw[];
    const uint32_t raw_u = smem_u32(smraw);
    const uint32_t abase = (raw_u + 1023u) & ~1023u;
    char* base = smraw + (abase - raw_u);

    const int tid  = threadIdx.x;
    const int wid  = tid >> 5;          // 0..15, owns m16-tile wid
    const int lane = tid & 31;
    const int img0 = blockIdx.x * IMG_PER_CTA;
    const int n_img = (I_N - img0 < IMG_PER_CTA) ? (I_N - img0) : IMG_PER_CTA;

    float* rmaxb = (float*)(base + OFF_RMAX);  // [2][8][256]
    float* inv   = (float*)(base + OFF_INV);
    if (tid < n_img)
        inv[tid] = 1.0f / ((float)im_l[img0 + tid] + 1e-6f);

    // ---- stage A into swizzled smem; zero-pad rows >= n_img*36 ----
    {
        const int vchunks = n_img * O_N * 8;
        const uint4* ga = (const uint4*)(gA + (size_t)img0 * O_N * D_N);
        const uint4 z = make_uint4(0, 0, 0, 0);
        #pragma unroll
        for (int t = tid; t < 2048; t += THREADS) {
            uint32_t off = SW128((uint32_t)(t * 16));
            *(uint4*)(base + OFF_A + off) = (t < vchunks) ? ga[t] : z;
        }
    }

    // ---- prefetch B batch 0 (captions 0..7): 64 KB ----
    {
        const char* sh = (const char*)(gBh);
        uint32_t dst = abase + OFF_B;
        #pragma unroll
        for (int t = tid; t < 4096; t += THREADS) {
            uint32_t off = SW128((uint32_t)(t * 16));
            CP16(dst + off, sh + t * 16);
        }
    }
    CP_COMMIT();

    // ---- ldmatrix addressing invariants ----
    const uint32_t xr    = (uint32_t)((lane & 7) << 4);
    const uint32_t aColB = (uint32_t)((lane >> 4) << 4);
    const uint32_t aRow  = (uint32_t)(wid * 16 + (lane & 15));
    // B ldsm4: lane L -> row (L&7), matrix (L>>3); one x4 covers 2 k-steps.
    const uint32_t bRowOff = (uint32_t)((lane & 7) * 128);
    const uint32_t bMat    = (uint32_t)((lane >> 3) << 4);

    // epilogue mapping: quad q (0..55) -> (image q>>3, caption q&7)
    const int quad = tid >> 2;
    const int ql   = tid & 3;
    const int eimg = quad >> 3;
    const int ecap = quad & 7;
    const bool edo = (quad < 56) && (eimg < n_img);

    __syncthreads();   // A staged (needed before ldsm of A)

    // ---- A fragments resident in registers (one m-tile per warp) ----
    uint32_t af[4][4];
    #pragma unroll
    for (int k = 0; k < 4; ++k)
        ldsm4(af[k], abase + OFF_A + aRow * 128 + ((aColB + (uint32_t)(k * 32)) ^ xr));

    for (int cc = 0; cc < NBATCH; ++cc) {
        // prefetch next batch (64 KB)
        if (cc + 1 < NBATCH) {
            const char* sh = (const char*)(gBh + (size_t)(cc + 1) * 32768);
            uint32_t dst = abase + OFF_B + (uint32_t)((cc + 1) & 1) * 65536;
            #pragma unroll
            for (int t = tid; t < 4096; t += THREADS) {
                uint32_t off = SW128((uint32_t)(t * 16));
                CP16(dst + off, sh + t * 16);
            }
            CP_COMMIT();
            CP_WAIT(1);
        } else {
            CP_WAIT(0);
        }
        // ONE barrier per batch: orders (a) B(cc) visibility for all warps,
        // (b) completeness of rmax(cc-1) writes, (c) WAR: all reads of
        // rmax(cc) buffer (done in epilogue of cc-1, two iterations back)
        // precede this point.
        __syncthreads();

        // ---- deferred score epilogue for batch cc-1 (reads buf (cc-1)&1) ----
        if (cc > 0 && edo) {
            const float* rj = rmaxb + (uint32_t)((cc - 1) & 1) * 2048
                             + ecap * 256 + eimg * O_N;
            float v = 0.0f;
            #pragma unroll
            for (int i = 0; i < 9; ++i)
                v += rj[ql + 4 * i];
            v += __shfl_xor_sync(0xFFFFFFFFu, v, 1);
            v += __shfl_xor_sync(0xFFFFFFFFu, v, 2);
            if (ql == 0)
                g_scores[(size_t)(img0 + eimg) * C_N + CAP_BATCH * (cc - 1) + ecap] =
                    v * inv[eimg];
        }

        float* rmax = rmaxb + (uint32_t)(cc & 1) * 2048;   // write buf cc&1

        #pragma unroll
        for (int j = 0; j < CAP_BATCH; ++j) {
            const int c = CAP_BATCH * cc + j;
            const int clen = __ldg(&s_l[c]);
            const int nlim = (clen + 7) >> 3;      // n8 tiles to compute
            const uint32_t bh_base = abase + OFF_B + (uint32_t)((cc & 1) << 16)
                                    + (uint32_t)(j << 13);

            float mx[2] = { -1e30f, -1e30f };

            #pragma unroll
            for (int p = 0; p < 4; ++p) {
                const int n0 = 2 * p;
                if (n0 < nlim) {
                    const bool has2 = (n0 + 1) < nlim;
                    // bf[kp][0..3]: {r0,r1}=k-step 2kp, {r2,r3}=k-step 2kp+1
                    uint32_t bf0[2][4], bf1[2][4];
                    #pragma unroll
                    for (int kp = 0; kp < 2; ++kp)
                        ldsm4(bf0[kp], bh_base + (uint32_t)(n0 * 1024) + bRowOff
                                      + (((uint32_t)(kp * 64) + bMat) ^ xr));
                    if (has2) {
                        #pragma unroll
                        for (int kp = 0; kp < 2; ++kp)
                            ldsm4(bf1[kp], bh_base + (uint32_t)((n0 + 1) * 1024) + bRowOff
                                          + (((uint32_t)(kp * 64) + bMat) ^ xr));
                    }

                    float acc[2][4];
                    #pragma unroll
                    for (int t2 = 0; t2 < 2; ++t2)
                        #pragma unroll
                        for (int q = 0; q < 4; ++q) acc[t2][q] = 0.0f;

                    #pragma unroll
                    for (int k = 0; k < 4; ++k) {
                        mma16816(acc[0], af[k], &bf0[k >> 1][(k & 1) * 2]);
                        if (has2)
                            mma16816(acc[1], af[k], &bf1[k >> 1][(k & 1) * 2]);
                    }

                    mx[0] = fmaxf(mx[0], fmaxf(acc[0][0], acc[0][1]));
                    mx[1] = fmaxf(mx[1], fmaxf(acc[0][2], acc[0][3]));
                    if (has2) {
                        mx[0] = fmaxf(mx[0], fmaxf(acc[1][0], acc[1][1]));
                        mx[1] = fmaxf(mx[1], fmaxf(acc[1][2], acc[1][3]));
                    }
                }
            }

            // quad reduce (lanes sharing the same rows)
            #pragma unroll
            for (int q = 0; q < 2; ++q) {
                mx[q] = fmaxf(mx[q], __shfl_xor_sync(0xFFFFFFFFu, mx[q], 1));
                mx[q] = fmaxf(mx[q], __shfl_xor_sync(0xFFFFFFFFu, mx[q], 2));
            }
            if ((lane & 3) == 0) {
                float* rj = rmax + j * 256;
                const int row0 = wid * 16 + (lane >> 2);
                rj[row0]     = mx[0];
                rj[row0 + 8] = mx[1];
            }
        }
    }

    // ---- final batch's epilogue ----
    __syncthreads();
    if (edo) {
        const float* rj = rmaxb + (uint32_t)((NBATCH - 1) & 1) * 2048
                         + ecap * 256 + eimg * O_N;
        float v = 0.0f;
        #pragma unroll
        for (int i = 0; i < 9; ++i)
            v += rj[ql + 4 * i];
        v += __shfl_xor_sync(0xFFFFFFFFu, v, 1);
        v += __shfl_xor_sync(0xFFFFFFFFu, v, 2);
        if (ql == 0)
            g_scores[(size_t)(img0 + eimg) * C_N + CAP_BATCH * (NBATCH - 1) + ecap] =
                v * inv[eimg];
    }
}

// ---------------- loss epilogue ----------------
extern "C" __global__ void diag_kernel()
{
    int i = blockIdx.x * blockDim.x + threadIdx.x;
    if (i < I_N) g_diag[i] = g_scores[(size_t)i * C_N + i];
}

extern "C" __global__ void row_kernel()
{
    const int b = blockIdx.x;
    const int tid = threadIdx.x;
    const float di = g_diag[b];
    float local = 0.0f;
    for (int c = tid; c < C_N; c += blockDim.x) {
        if (c == b) continue;
        float sc = g_scores[(size_t)b * C_N + c];
        local += fmaxf(0.0f, MARGIN + sc - di)
               + fmaxf(0.0f, MARGIN + sc - g_diag[c]);
    }
    __shared__ float buf[128];
    buf[tid] = local;
    __syncthreads();
    for (int s = 64; s > 0; s >>= 1) {
        if (tid < s) buf[tid] += buf[tid + s];
        __syncthreads();
    }
    if (tid == 0) g_partial[b] = buf[0];
}

extern "C" __global__ void final_kernel(float* out)
{
    const int tid = threadIdx.x;
    float local = 0.0f;
    for (int i = tid; i < I_N; i += 256) local += g_partial[i];
    __shared__ float buf[256];
    buf[tid] = local;
    __syncthreads();
    for (int s = 128; s > 0; s >>= 1) {
        if (tid < s) buf[tid] += buf[tid + s];
        __syncthreads();
    }
    if (tid == 0) out[0] = buf[0] * (1.0f / ((float)I_N * (float)C_N));
}

// ---------------- launch ----------------
extern "C" void kernel_launch(void* const* d_in, const int* in_sizes, int n_in,
                              void* d_out, int out_size)
{
    const float* im   = (const float*)d_in[0];
    const float* s    = (const float*)d_in[1];
    const int*   im_l = (const int*)d_in[2];
    const int*   s_l  = (const int*)d_in[3];

    cudaFuncSetAttribute(xattn_kernel,
                         cudaFuncAttributeMaxDynamicSharedMemorySize, SMEM_BYTES);

    convA_kernel<<<(I_N * O_N * D_N + 255) / 256, 256>>>(im);
    convB_kernel<<<(C_N * 64 * D_N + 255) / 256, 256>>>(s, s_l);
    xattn_kernel<<<NCTA, THREADS, SMEM_BYTES>>>(im_l, s_l);
    diag_kernel<<<I_N / 256, 256>>>();
    row_kernel<<<I_N, 128>>>();
    final_kernel<<<1, 256>>>((float*)d_out);
}

// round 11
// speedup vs baseline: 1.0858x; 1.0117x over previous
#include <cuda_runtime.h>
#include <cuda_bf16.h>
#include <stdint.h>

// ---------------- problem constants ----------------
#define I_N 1024
#define O_N 36
#define C_N 1024
#define W_N 60
#define D_N 64
#define MARGIN 0.2f

#define IMG_PER_CTA 7
#define NCTA 147            // ceil(1024/7)
#define THREADS 512         // 16 warps; warp w owns m16-tile w (256 rows total)
#define CAP_BATCH 8         // captions per B buffer (8KB each, bf16)
#define NBATCH (C_N / CAP_BATCH)

// ---------------- smem layout (bytes from 1024-aligned base) ----------------
#define OFF_A    0          // 256 rows x 128B (bf16)            = 32768
#define OFF_B    32768      // 2 bufs x 64KB (8 captions each)   = 131072
#define OFF_RMAX 163840     // 2 bufs x 8 x 256 floats           = 16384
#define OFF_INV  180224     // 7 floats
#define SMEM_BYTES (180256 + 1024)

// ---------------- device globals ----------------
__device__ __nv_bfloat16 gA [(size_t)I_N * O_N * D_N];
__device__ __nv_bfloat16 gBh[(size_t)C_N * 64 * D_N];   // words padded to 64 w/ duplicate of last valid word
__device__ float g_scores[(size_t)I_N * C_N];
__device__ float g_diag[I_N];
__device__ float g_partial[I_N];

// ---------------- helpers ----------------
__device__ __forceinline__ uint32_t smem_u32(const void* p) {
    uint32_t a;
    asm("{ .reg .u64 t; cvta.to.shared.u64 t, %1; cvt.u32.u64 %0, t; }" : "=r"(a) : "l"(p));
    return a;
}
#define SW128(off) ((off) ^ (((off) >> 3) & 0x70))

__device__ __forceinline__ void ldsm4(uint32_t* r, uint32_t addr) {
    asm volatile("ldmatrix.sync.aligned.m8n8.x4.shared.b16 {%0,%1,%2,%3}, [%4];"
                 : "=r"(r[0]), "=r"(r[1]), "=r"(r[2]), "=r"(r[3]) : "r"(addr));
}
__device__ __forceinline__ void mma16816(float* d, const uint32_t* a, const uint32_t* b) {
    asm volatile(
        "mma.sync.aligned.m16n8k16.row.col.f32.bf16.bf16.f32 "
        "{%0,%1,%2,%3}, {%4,%5,%6,%7}, {%8,%9}, {%0,%1,%2,%3};"
        : "+f"(d[0]), "+f"(d[1]), "+f"(d[2]), "+f"(d[3])
        : "r"(a[0]), "r"(a[1]), "r"(a[2]), "r"(a[3]), "r"(b[0]), "r"(b[1]));
}
#define CP16(dst, src) \
    asm volatile("cp.async.cg.shared.global [%0], [%1], 16;" :: "r"(dst), "l"(src))
#define CP_COMMIT()  asm volatile("cp.async.commit_group;" ::: "memory")
#define CP_WAIT(n)   asm volatile("cp.async.wait_group %0;" :: "n"(n) : "memory")

// ---------------- fused precompute: A convert + B convert/pad ----------------
// elems [0, NA) -> gA ; elems [NA, NA+NB) -> gBh
#define NA (I_N * O_N * D_N)
#define NB (C_N * 64 * D_N)
extern "C" __global__ void conv_kernel(const float* __restrict__ im,
                                       const float* __restrict__ s,
                                       const int* __restrict__ s_l)
{
    size_t idx = (size_t)blockIdx.x * blockDim.x + threadIdx.x;
    if (idx < (size_t)NA) {
        gA[idx] = __float2bfloat16(im[idx]);
    } else if (idx < (size_t)NA + NB) {
        size_t b = idx - NA;
        int d = (int)(b & 63);
        int w = ((int)(b >> 6)) & 63;
        int c = (int)(b >> 12);
        int clen = s_l[c];
        // Pad words [clen, 64) with a COPY of word clen-1: max over any computed
        // superset of columns equals the true max -> no masking downstream.
        int ws = (w < clen) ? w : (clen - 1);
        gBh[b] = __float2bfloat16(s[((size_t)c * W_N + ws) * D_N + d]);
    }
}

// ---------------- main xattn-scores kernel ----------------
extern "C" __global__ void __launch_bounds__(THREADS, 1)
xattn_kernel(const int* __restrict__ im_l, const int* __restrict__ s_l)
{
    extern __shared__ char smraw[];
    const uint32_t raw_u = smem_u32(smraw);
    const uint32_t abase = (raw_u + 1023u) & ~1023u;
    char* base = smraw + (abase - raw_u);

    const int tid  = threadIdx.x;
    const int wid  = tid >> 5;          // 0..15, owns m16-tile wid
    const int lane = tid & 31;
    const int img0 = blockIdx.x * IMG_PER_CTA;
    const int n_img = (I_N - img0 < IMG_PER_CTA) ? (I_N - img0) : IMG_PER_CTA;

    float* rmaxb = (float*)(base + OFF_RMAX);  // [2][8][256]
    float* inv   = (float*)(base + OFF_INV);
    if (tid < n_img)
        inv[tid] = 1.0f / ((float)im_l[img0 + tid] + 1e-6f);

    // ---- stage A into swizzled smem; zero-pad rows >= n_img*36 ----
    {
        const int vchunks = n_img * O_N * 8;
        const uint4* ga = (const uint4*)(gA + (size_t)img0 * O_N * D_N);
        const uint4 z = make_uint4(0, 0, 0, 0);
        #pragma unroll
        for (int t = tid; t < 2048; t += THREADS) {
            uint32_t off = SW128((uint32_t)(t * 16));
            *(uint4*)(base + OFF_A + off) = (t < vchunks) ? ga[t] : z;
        }
    }

    // ---- prefetch B batch 0 (captions 0..7): 64 KB ----
    {
        const char* sh = (const char*)(gBh);
        uint32_t dst = abase + OFF_B;
        #pragma unroll
        for (int t = tid; t < 4096; t += THREADS) {
            uint32_t off = SW128((uint32_t)(t * 16));
            CP16(dst + off, sh + t * 16);
        }
    }
    CP_COMMIT();

    // ---- ldmatrix addressing invariants ----
    const uint32_t xr    = (uint32_t)((lane & 7) << 4);
    const uint32_t aColB = (uint32_t)((lane >> 4) << 4);
    const uint32_t aRow  = (uint32_t)(wid * 16 + (lane & 15));
    // B ldsm4: lane L -> row (L&7), matrix (L>>3); one x4 covers 2 k-steps.
    const uint32_t bRowOff = (uint32_t)((lane & 7) * 128);
    const uint32_t bMat    = (uint32_t)((lane >> 3) << 4);

    // epilogue mapping: quad q (0..55) -> (image q>>3, caption q&7)
    const int quad = tid >> 2;
    const int ql   = tid & 3;
    const int eimg = quad >> 3;
    const int ecap = quad & 7;
    const bool edo = (quad < 56) && (eimg < n_img);

    __syncthreads();   // A staged (needed before ldsm of A)

    // ---- A fragments resident in registers (one m-tile per warp) ----
    uint32_t af[4][4];
    #pragma unroll
    for (int k = 0; k < 4; ++k)
        ldsm4(af[k], abase + OFF_A + aRow * 128 + ((aColB + (uint32_t)(k * 32)) ^ xr));

    for (int cc = 0; cc < NBATCH; ++cc) {
        // prefetch next batch (64 KB)
        if (cc + 1 < NBATCH) {
            const char* sh = (const char*)(gBh + (size_t)(cc + 1) * 32768);
            uint32_t dst = abase + OFF_B + (uint32_t)((cc + 1) & 1) * 65536;
            #pragma unroll
            for (int t = tid; t < 4096; t += THREADS) {
                uint32_t off = SW128((uint32_t)(t * 16));
                CP16(dst + off, sh + t * 16);
            }
            CP_COMMIT();
            CP_WAIT(1);
        } else {
            CP_WAIT(0);
        }
        // ONE barrier per batch: orders (a) B(cc) visibility for all warps,
        // (b) completeness of rmax(cc-1) writes, (c) WAR on rmax(cc) buffer.
        __syncthreads();

        // ---- deferred score epilogue for batch cc-1 (reads buf (cc-1)&1) ----
        if (cc > 0 && edo) {
            const float* rj = rmaxb + (uint32_t)((cc - 1) & 1) * 2048
                             + ecap * 256 + eimg * O_N;
            float v = 0.0f;
            #pragma unroll
            for (int i = 0; i < 9; ++i)
                v += rj[ql + 4 * i];
            v += __shfl_xor_sync(0xFFFFFFFFu, v, 1);
            v += __shfl_xor_sync(0xFFFFFFFFu, v, 2);
            if (ql == 0) {
                const int gc = CAP_BATCH * (cc - 1) + ecap;
                const int gr = img0 + eimg;
                float sc = v * inv[eimg];
                g_scores[(size_t)gr * C_N + gc] = sc;
                if (gr == gc) g_diag[gc] = sc;   // fused diag extraction
            }
        }

        // batch caption lengths: 2 vector LDGs instead of 8 scalar LDGs
        const int4 cl0 = *(const int4*)(s_l + CAP_BATCH * cc);
        const int4 cl1 = *(const int4*)(s_l + CAP_BATCH * cc + 4);
        const int clens[8] = { cl0.x, cl0.y, cl0.z, cl0.w,
                               cl1.x, cl1.y, cl1.z, cl1.w };

        float* rmax = rmaxb + (uint32_t)(cc & 1) * 2048;   // write buf cc&1

        #pragma unroll
        for (int j = 0; j < CAP_BATCH; ++j) {
            const int nlim = (clens[j] + 7) >> 3;  // n8 tiles to compute
            const uint32_t bh_base = abase + OFF_B + (uint32_t)((cc & 1) << 16)
                                    + (uint32_t)(j << 13);

            float mx[2] = { -1e30f, -1e30f };

            #pragma unroll
            for (int p = 0; p < 4; ++p) {
                const int n0 = 2 * p;
                if (n0 < nlim) {
                    const bool has2 = (n0 + 1) < nlim;
                    // bf[kp][0..3]: {r0,r1}=k-step 2kp, {r2,r3}=k-step 2kp+1
                    uint32_t bf0[2][4], bf1[2][4];
                    #pragma unroll
                    for (int kp = 0; kp < 2; ++kp)
                        ldsm4(bf0[kp], bh_base + (uint32_t)(n0 * 1024) + bRowOff
                                      + (((uint32_t)(kp * 64) + bMat) ^ xr));
                    if (has2) {
                        #pragma unroll
                        for (int kp = 0; kp < 2; ++kp)
                            ldsm4(bf1[kp], bh_base + (uint32_t)((n0 + 1) * 1024) + bRowOff
                                          + (((uint32_t)(kp * 64) + bMat) ^ xr));
                    }

                    float acc[2][4];
                    #pragma unroll
                    for (int t2 = 0; t2 < 2; ++t2)
                        #pragma unroll
                        for (int q = 0; q < 4; ++q) acc[t2][q] = 0.0f;

                    #pragma unroll
                    for (int k = 0; k < 4; ++k) {
                        mma16816(acc[0], af[k], &bf0[k >> 1][(k & 1) * 2]);
                        if (has2)
                            mma16816(acc[1], af[k], &bf1[k >> 1][(k & 1) * 2]);
                    }

                    mx[0] = fmaxf(mx[0], fmaxf(acc[0][0], acc[0][1]));
                    mx[1] = fmaxf(mx[1], fmaxf(acc[0][2], acc[0][3]));
                    if (has2) {
                        mx[0] = fmaxf(mx[0], fmaxf(acc[1][0], acc[1][1]));
                        mx[1] = fmaxf(mx[1], fmaxf(acc[1][2], acc[1][3]));
                    }
                }
            }

            // quad reduce (lanes sharing the same rows)
            #pragma unroll
            for (int q = 0; q < 2; ++q) {
                mx[q] = fmaxf(mx[q], __shfl_xor_sync(0xFFFFFFFFu, mx[q], 1));
                mx[q] = fmaxf(mx[q], __shfl_xor_sync(0xFFFFFFFFu, mx[q], 2));
            }
            if ((lane & 3) == 0) {
                float* rj = rmax + j * 256;
                const int row0 = wid * 16 + (lane >> 2);
                rj[row0]     = mx[0];
                rj[row0 + 8] = mx[1];
            }
        }
    }

    // ---- final batch's epilogue ----
    __syncthreads();
    if (edo) {
        const float* rj = rmaxb + (uint32_t)((NBATCH - 1) & 1) * 2048
                         + ecap * 256 + eimg * O_N;
        float v = 0.0f;
        #pragma unroll
        for (int i = 0; i < 9; ++i)
            v += rj[ql + 4 * i];
        v += __shfl_xor_sync(0xFFFFFFFFu, v, 1);
        v += __shfl_xor_sync(0xFFFFFFFFu, v, 2);
        if (ql == 0) {
            const int gc = CAP_BATCH * (NBATCH - 1) + ecap;
            const int gr = img0 + eimg;
            float sc = v * inv[eimg];
            g_scores[(size_t)gr * C_N + gc] = sc;
            if (gr == gc) g_diag[gc] = sc;
        }
    }
}

// ---------------- loss epilogue ----------------
extern "C" __global__ void row_kernel()
{
    const int b = blockIdx.x;
    const int tid = threadIdx.x;
    const float di = g_diag[b];
    float local = 0.0f;
    for (int c = tid; c < C_N; c += blockDim.x) {
        if (c == b) continue;
        float sc = g_scores[(size_t)b * C_N + c];
        local += fmaxf(0.0f, MARGIN + sc - di)
               + fmaxf(0.0f, MARGIN + sc - g_diag[c]);
    }
    __shared__ float buf[128];
    buf[tid] = local;
    __syncthreads();
    for (int s = 64; s > 0; s >>= 1) {
        if (tid < s) buf[tid] += buf[tid + s];
        __syncthreads();
    }
    if (tid == 0) g_partial[b] = buf[0];
}

extern "C" __global__ void final_kernel(float* out)
{
    const int tid = threadIdx.x;
    float local = 0.0f;
    for (int i = tid; i < I_N; i += 256) local += g_partial[i];
    __shared__ float buf[256];
    buf[tid] = local;
    __syncthreads();
    for (int s = 128; s > 0; s >>= 1) {
        if (tid < s) buf[tid] += buf[tid + s];
        __syncthreads();
    }
    if (tid == 0) out[0] = buf[0] * (1.0f / ((float)I_N * (float)C_N));
}

// ---------------- launch ----------------
extern "C" void kernel_launch(void* const* d_in, const int* in_sizes, int n_in,
                              void* d_out, int out_size)
{
    const float* im   = (const float*)d_in[0];
    const float* s    = (const float*)d_in[1];
    const int*   im_l = (const int*)d_in[2];
    const int*   s_l  = (const int*)d_in[3];

    cudaFuncSetAttribute(xattn_kernel,
                         cudaFuncAttributeMaxDynamicSharedMemorySize, SMEM_BYTES);

    conv_kernel<<<(NA + NB + 255) / 256, 256>>>(im, s, s_l);
    xattn_kernel<<<NCTA, THREADS, SMEM_BYTES>>>(im_l, s_l);
    row_kernel<<<I_N, 128>>>();
    final_kernel<<<1, 256>>>((float*)d_out);
}